// round 2
// baseline (speedup 1.0000x reference)
#include <cuda_runtime.h>
#include <math.h>

#define N_NODES 100000
#define N_EDGES 400000
#define N_GRAPHS 4096
#define D0 78
#define D1 78
#define D2 156
#define D3 312
#define DH 1024
#define DOUT 128

// ---------------- scratch (device globals; no allocation allowed) ----------------
__device__ float g_A[(size_t)N_NODES * D3];      // activations / agg buffer
__device__ float g_B[(size_t)N_NODES * D3];      // xW buffer
__device__ float g_dinv[N_NODES];
__device__ float g_pool[(size_t)N_GRAPHS * D3];
__device__ float g_cnt[N_GRAPHS];
__device__ float g_g[(size_t)N_GRAPHS * D3];
__device__ float g_fused[(size_t)N_GRAPHS * D3];
__device__ float g_h[(size_t)N_GRAPHS * DH];

// ---------------- utility kernels ----------------
__global__ void zero_kernel(float* __restrict__ p, size_t n) {
    size_t i = (size_t)blockIdx.x * blockDim.x + threadIdx.x;
    if (i < n) p[i] = 0.0f;
}

__global__ void deg_init_kernel(float* __restrict__ deg) {
    int i = blockIdx.x * blockDim.x + threadIdx.x;
    if (i < N_NODES) deg[i] = 1.0f;   // self-loop
}

__global__ void deg_count_kernel(const int* __restrict__ dst, float* __restrict__ deg) {
    int e = blockIdx.x * blockDim.x + threadIdx.x;
    if (e < N_EDGES) atomicAdd(&deg[dst[e]], 1.0f);
}

__global__ void deg_rsqrt_kernel(float* __restrict__ dinv) {
    int i = blockIdx.x * blockDim.x + threadIdx.x;
    if (i < N_NODES) dinv[i] = rsqrtf(dinv[i]);
}

// ---------------- tiled fp32 GEMM: C[M,N] = A[M,K] @ B[K,N] (+bias)(+relu) ----------------
// 64x64 tile, BK=16, 256 threads, 4x4 microtile per thread.
#define GBM 64
#define GBN 64
#define GBK 16
__global__ __launch_bounds__(256) void gemm_kernel(
    const float* __restrict__ A, const float* __restrict__ B,
    const float* __restrict__ bias, float* __restrict__ C,
    int M, int K, int N, int mode /*0=none,1=bias,2=bias+relu*/) {
    __shared__ float As[GBK][GBM];
    __shared__ float Bs[GBK][GBN + 4];
    int tid = threadIdx.x;
    int tx = tid & 15;        // N dir
    int ty = tid >> 4;        // M dir
    int row0 = blockIdx.y * GBM;
    int col0 = blockIdx.x * GBN;

    float acc[4][4] = {};
    for (int k0 = 0; k0 < K; k0 += GBK) {
        // load A tile (64x16 = 1024 elems)
        #pragma unroll
        for (int t = 0; t < 4; t++) {
            int idx = tid + t * 256;
            int m = idx >> 4;          // idx / GBK
            int kk = idx & 15;         // idx % GBK
            int gm = row0 + m, gk = k0 + kk;
            As[kk][m] = (gm < M && gk < K) ? A[(size_t)gm * K + gk] : 0.0f;
        }
        // load B tile (16x64)
        #pragma unroll
        for (int t = 0; t < 4; t++) {
            int idx = tid + t * 256;
            int kk = idx >> 6;         // idx / GBN
            int n  = idx & 63;         // idx % GBN
            int gk = k0 + kk, gn = col0 + n;
            Bs[kk][n] = (gk < K && gn < N) ? B[(size_t)gk * N + gn] : 0.0f;
        }
        __syncthreads();
        #pragma unroll
        for (int kk = 0; kk < GBK; kk++) {
            float a[4], b[4];
            #pragma unroll
            for (int i = 0; i < 4; i++) a[i] = As[kk][ty * 4 + i];
            #pragma unroll
            for (int j = 0; j < 4; j++) b[j] = Bs[kk][tx * 4 + j];
            #pragma unroll
            for (int i = 0; i < 4; i++)
                #pragma unroll
                for (int j = 0; j < 4; j++)
                    acc[i][j] = fmaf(a[i], b[j], acc[i][j]);
        }
        __syncthreads();
    }
    #pragma unroll
    for (int i = 0; i < 4; i++) {
        int gm = row0 + ty * 4 + i;
        if (gm >= M) continue;
        #pragma unroll
        for (int j = 0; j < 4; j++) {
            int gn = col0 + tx * 4 + j;
            if (gn >= N) continue;
            float v = acc[i][j];
            if (mode >= 1) v += bias[gn];
            if (mode == 2) v = fmaxf(v, 0.0f);
            C[(size_t)gm * N + gn] = v;
        }
    }
}

// ---------------- edge scatter: A[dst] += B[src] * dinv[src]*dinv[dst] ----------------
// one warp per edge, lanes stride features
__global__ __launch_bounds__(256) void edge_scatter_kernel(
    const float* __restrict__ B, float* __restrict__ A,
    const int* __restrict__ src, const int* __restrict__ dst,
    const float* __restrict__ dinv, int Dout) {
    int warp = (blockIdx.x * blockDim.x + threadIdx.x) >> 5;
    int lane = threadIdx.x & 31;
    if (warp >= N_EDGES) return;
    int s = src[warp];
    int d = dst[warp];
    float norm = dinv[s] * dinv[d];
    const float* __restrict__ brow = B + (size_t)s * Dout;
    float* __restrict__ arow = A + (size_t)d * Dout;
    for (int f = lane; f < Dout; f += 32)
        atomicAdd(&arow[f], brow[f] * norm);
}

// ---------------- finalize: A = relu(A + B*dinv^2 + bias) ----------------
__global__ void finalize_kernel(float* __restrict__ A, const float* __restrict__ B,
                                const float* __restrict__ bias,
                                const float* __restrict__ dinv, int Dout) {
    size_t idx = (size_t)blockIdx.x * blockDim.x + threadIdx.x;
    size_t total = (size_t)N_NODES * Dout;
    if (idx >= total) return;
    int i = (int)(idx / Dout);
    int f = (int)(idx % Dout);
    float di = dinv[i];
    float v = A[idx] + B[idx] * di * di + bias[f];
    A[idx] = fmaxf(v, 0.0f);
}

// ---------------- mean pool over graphs ----------------
__global__ __launch_bounds__(256) void pool_kernel(
    const float* __restrict__ X, const int* __restrict__ batch,
    float* __restrict__ pooled, float* __restrict__ cnt) {
    int warp = (blockIdx.x * blockDim.x + threadIdx.x) >> 5;
    int lane = threadIdx.x & 31;
    if (warp >= N_NODES) return;
    int g = batch[warp];
    if (lane == 0) atomicAdd(&cnt[g], 1.0f);
    const float* __restrict__ xrow = X + (size_t)warp * D3;
    float* __restrict__ prow = pooled + (size_t)g * D3;
    for (int f = lane; f < D3; f += 32)
        atomicAdd(&prow[f], xrow[f]);
}

__global__ void pool_div_kernel(float* __restrict__ pooled, const float* __restrict__ cnt) {
    int idx = blockIdx.x * blockDim.x + threadIdx.x;
    if (idx >= N_GRAPHS * D3) return;
    int g = idx / D3;
    pooled[idx] /= fmaxf(cnt[g], 1.0f);
}

// ---------------- gate + fuse: one warp per graph ----------------
__global__ __launch_bounds__(256) void gate_fuse_kernel(
    const float* __restrict__ pooled, const float* __restrict__ gvec,
    const float* __restrict__ Wgate, const float* __restrict__ bgate,
    float* __restrict__ fused) {
    int warp = (blockIdx.x * blockDim.x + threadIdx.x) >> 5;
    int lane = threadIdx.x & 31;
    if (warp >= N_GRAPHS) return;
    const float* __restrict__ prow = pooled + (size_t)warp * D3;
    const float* __restrict__ grow = gvec + (size_t)warp * D3;
    float t = 0.0f;
    for (int f = lane; f < D3; f += 32)
        t += prow[f] * Wgate[f] + grow[f] * Wgate[D3 + f];
    #pragma unroll
    for (int off = 16; off > 0; off >>= 1)
        t += __shfl_xor_sync(0xFFFFFFFF, t, off);
    t += bgate[0];
    float gate = 1.0f / (1.0f + expf(-t));
    gate = __shfl_sync(0xFFFFFFFF, gate, 0);
    float* __restrict__ frow = fused + (size_t)warp * D3;
    for (int f = lane; f < D3; f += 32)
        frow[f] = gate * grow[f] + (1.0f - gate) * prow[f];
}

// ---------------- host ----------------
static inline int cdiv(int a, int b) { return (a + b - 1) / b; }

extern "C" void kernel_launch(void* const* d_in, const int* in_sizes, int n_in,
                              void* d_out, int out_size) {
    const float* mol_x  = (const float*)d_in[0];
    const int*   edges  = (const int*)d_in[1];
    const int*   batch  = (const int*)d_in[2];
    const float* gemb   = (const float*)d_in[3];
    const float* W1     = (const float*)d_in[4];
    const float* b1     = (const float*)d_in[5];
    const float* W2     = (const float*)d_in[6];
    const float* b2     = (const float*)d_in[7];
    const float* W3     = (const float*)d_in[8];
    const float* b3     = (const float*)d_in[9];
    const float* Wfc1   = (const float*)d_in[10];
    const float* bfc1   = (const float*)d_in[11];
    const float* Wfc2   = (const float*)d_in[12];
    const float* bfc2   = (const float*)d_in[13];
    const float* Wproj  = (const float*)d_in[14];
    const float* bproj  = (const float*)d_in[15];
    const float* Wgate  = (const float*)d_in[16];
    const float* bgate  = (const float*)d_in[17];
    float* out = (float*)d_out;

    const int* src = edges;
    const int* dst = edges + N_EDGES;

    float *pA, *pB, *pdinv, *ppool, *pcnt, *pg, *pfused, *ph;
    cudaGetSymbolAddress((void**)&pA, g_A);
    cudaGetSymbolAddress((void**)&pB, g_B);
    cudaGetSymbolAddress((void**)&pdinv, g_dinv);
    cudaGetSymbolAddress((void**)&ppool, g_pool);
    cudaGetSymbolAddress((void**)&pcnt, g_cnt);
    cudaGetSymbolAddress((void**)&pg, g_g);
    cudaGetSymbolAddress((void**)&pfused, g_fused);
    cudaGetSymbolAddress((void**)&ph, g_h);

    // ---- degree + dinv ----
    deg_init_kernel<<<cdiv(N_NODES, 256), 256>>>(pdinv);
    deg_count_kernel<<<cdiv(N_EDGES, 256), 256>>>(dst, pdinv);
    deg_rsqrt_kernel<<<cdiv(N_NODES, 256), 256>>>(pdinv);

    // ---- GCN layer helper (inline) ----
    // layer(X, Din, Dout, W, b): B = X@W ; A = 0 ; scatter ; A = relu(A + B*dinv^2 + b)
    {
        // Layer 1: mol_x [N,78] -> A [N,78]
        dim3 grid1(cdiv(D1, GBN), cdiv(N_NODES, GBM));
        gemm_kernel<<<grid1, 256>>>(mol_x, W1, nullptr, pB, N_NODES, D0, D1, 0);
        size_t n1 = (size_t)N_NODES * D1;
        zero_kernel<<<(unsigned)((n1 + 255) / 256), 256>>>(pA, n1);
        edge_scatter_kernel<<<cdiv(N_EDGES * 32, 256), 256>>>(pB, pA, src, dst, pdinv, D1);
        finalize_kernel<<<(unsigned)((n1 + 255) / 256), 256>>>(pA, pB, b1, pdinv, D1);
    }
    {
        // Layer 2: A [N,78] -> A [N,156]
        dim3 grid2(cdiv(D2, GBN), cdiv(N_NODES, GBM));
        gemm_kernel<<<grid2, 256>>>(pA, W2, nullptr, pB, N_NODES, D1, D2, 0);
        size_t n2 = (size_t)N_NODES * D2;
        zero_kernel<<<(unsigned)((n2 + 255) / 256), 256>>>(pA, n2);
        edge_scatter_kernel<<<cdiv(N_EDGES * 32, 256), 256>>>(pB, pA, src, dst, pdinv, D2);
        finalize_kernel<<<(unsigned)((n2 + 255) / 256), 256>>>(pA, pB, b2, pdinv, D2);
    }
    {
        // Layer 3: A [N,156] -> A [N,312]
        dim3 grid3(cdiv(D3, GBN), cdiv(N_NODES, GBM));
        gemm_kernel<<<grid3, 256>>>(pA, W3, nullptr, pB, N_NODES, D2, D3, 0);
        size_t n3 = (size_t)N_NODES * D3;
        zero_kernel<<<(unsigned)((n3 + 255) / 256), 256>>>(pA, n3);
        edge_scatter_kernel<<<cdiv(N_EDGES * 32, 256), 256>>>(pB, pA, src, dst, pdinv, D3);
        finalize_kernel<<<(unsigned)((n3 + 255) / 256), 256>>>(pA, pB, b3, pdinv, D3);
    }

    // ---- mean pool ----
    {
        size_t np = (size_t)N_GRAPHS * D3;
        zero_kernel<<<(unsigned)((np + 255) / 256), 256>>>(ppool, np);
        zero_kernel<<<cdiv(N_GRAPHS, 256), 256>>>(pcnt, (size_t)N_GRAPHS);
        pool_kernel<<<cdiv(N_NODES * 32, 256), 256>>>(pA, batch, ppool, pcnt);
        pool_div_kernel<<<cdiv(N_GRAPHS * D3, 256), 256>>>(ppool, pcnt);
    }

    // ---- g = global_emb @ Wproj + bproj  [4096,128]@[128,312] ----
    {
        dim3 gridp(cdiv(D3, GBN), cdiv(N_GRAPHS, GBM));
        gemm_kernel<<<gridp, 256>>>(gemb, Wproj, bproj, pg, N_GRAPHS, 128, D3, 1);
    }

    // ---- gate + fuse ----
    gate_fuse_kernel<<<cdiv(N_GRAPHS * 32, 256), 256>>>(ppool, pg, Wgate, bgate, pfused);

    // ---- fc1: relu(fused @ Wfc1 + bfc1)  [4096,312]@[312,1024] ----
    {
        dim3 gridf1(cdiv(DH, GBN), cdiv(N_GRAPHS, GBM));
        gemm_kernel<<<gridf1, 256>>>(pfused, Wfc1, bfc1, ph, N_GRAPHS, D3, DH, 2);
    }

    // ---- fc2: h @ Wfc2 + bfc2  [4096,1024]@[1024,128] -> out ----
    {
        dim3 gridf2(cdiv(DOUT, GBN), cdiv(N_GRAPHS, GBM));
        gemm_kernel<<<gridf2, 256>>>(ph, Wfc2, bfc2, out, N_GRAPHS, DH, DOUT, 1);
    }
}

// round 4
// speedup vs baseline: 1.4595x; 1.4595x over previous
#include <cuda_runtime.h>
#include <math.h>

#define N_NODES 100000
#define N_EDGES 400000
#define N_GRAPHS 4096
#define D0 78
#define D1 78
#define D2 156
#define D3 312
#define DH 1024
#define DOUT 128

// ---------------- scratch (device globals; no allocation allowed) ----------------
__device__ float g_A[(size_t)N_NODES * D3];      // activations
__device__ float g_B[(size_t)N_NODES * D3];      // xw * dinv buffer
__device__ float g_dinv[N_NODES];
__device__ int   g_cnt[N_NODES];                 // in-degree (no self loop)
__device__ int   g_rowstart[N_NODES];
__device__ int   g_cursor[N_NODES];
__device__ int   g_blocksum[512];
__device__ int   g_csr_src[N_EDGES];
__device__ float g_pool[(size_t)N_GRAPHS * D3];
__device__ float g_gcnt[N_GRAPHS];
__device__ float g_g[(size_t)N_GRAPHS * D3];
__device__ float g_fused[(size_t)N_GRAPHS * D3];
__device__ float g_h[(size_t)N_GRAPHS * DH];

// ---------------- utility ----------------
__global__ void zero_f_kernel(float* __restrict__ p, size_t n) {
    size_t i = (size_t)blockIdx.x * blockDim.x + threadIdx.x;
    if (i < n) p[i] = 0.0f;
}
__global__ void zero_i_kernel(int* __restrict__ p, int n) {
    int i = blockIdx.x * blockDim.x + threadIdx.x;
    if (i < n) p[i] = 0;
}
__global__ void deg_count_kernel(const int* __restrict__ dst, int* __restrict__ cnt) {
    int e = blockIdx.x * blockDim.x + threadIdx.x;
    if (e < N_EDGES) atomicAdd(&cnt[dst[e]], 1);
}
__global__ void dinv_kernel(const int* __restrict__ cnt, float* __restrict__ dinv) {
    int i = blockIdx.x * blockDim.x + threadIdx.x;
    if (i < N_NODES) dinv[i] = rsqrtf((float)cnt[i] + 1.0f);
}

// ---------------- exclusive scan of cnt -> rowstart (3 kernels) ----------------
#define SCAN_T 256
#define SCAN_V 4
__global__ void scan1_kernel(const int* __restrict__ cnt, int* __restrict__ partial,
                             int* __restrict__ blocksum, int n) {
    __shared__ int sdata[SCAN_T];
    int bid = blockIdx.x;
    int base = bid * SCAN_T * SCAN_V;
    int v[SCAN_V]; int s = 0;
    #pragma unroll
    for (int i = 0; i < SCAN_V; i++) {
        int idx = base + threadIdx.x * SCAN_V + i;
        v[i] = (idx < n) ? cnt[idx] : 0;
        s += v[i];
    }
    sdata[threadIdx.x] = s;
    __syncthreads();
    for (int off = 1; off < SCAN_T; off <<= 1) {
        int t = (threadIdx.x >= off) ? sdata[threadIdx.x - off] : 0;
        __syncthreads();
        sdata[threadIdx.x] += t;
        __syncthreads();
    }
    int run = sdata[threadIdx.x] - s;   // exclusive prefix of this thread
    #pragma unroll
    for (int i = 0; i < SCAN_V; i++) {
        int idx = base + threadIdx.x * SCAN_V + i;
        if (idx < n) partial[idx] = run;
        run += v[i];
    }
    if (threadIdx.x == SCAN_T - 1) blocksum[bid] = sdata[threadIdx.x];
}
__global__ void scan2_kernel(int* __restrict__ blocksum, int nb) {
    if (threadIdx.x == 0 && blockIdx.x == 0) {
        int run = 0;
        for (int i = 0; i < nb; i++) { int t = blocksum[i]; blocksum[i] = run; run += t; }
    }
}
__global__ void scan3_kernel(int* __restrict__ rowstart, const int* __restrict__ blocksum,
                             int* __restrict__ cursor, int n) {
    int idx = blockIdx.x * blockDim.x + threadIdx.x;
    if (idx < n) {
        int v = rowstart[idx] + blocksum[idx / (SCAN_T * SCAN_V)];
        rowstart[idx] = v;
        cursor[idx] = v;
    }
}
__global__ void csr_scatter_kernel(const int* __restrict__ src, const int* __restrict__ dst,
                                   int* __restrict__ cursor, int* __restrict__ csr_src) {
    int e = blockIdx.x * blockDim.x + threadIdx.x;
    if (e < N_EDGES) {
        int pos = atomicAdd(&cursor[dst[e]], 1);
        csr_src[pos] = src[e];
    }
}

// ---------------- fp32 GEMM: C[M,N] = A[M,K] @ B[K,N], fused epilogue ----------------
// 128x64 tile, BK=16, 128 threads, 8x8 microtile.
// mode: 0=none, 1=+bias, 2=relu(+bias), 3=*scale[row]  (scale = dinv)
#define BM 128
#define BN 64
#define BK 16
__global__ __launch_bounds__(128) void gemm_kernel(
    const float* __restrict__ A, const float* __restrict__ B,
    const float* __restrict__ bias, const float* __restrict__ scale,
    float* __restrict__ C, int M, int K, int N, int mode) {
    __shared__ float As[BK][BM + 4];
    __shared__ float Bs[BK][BN + 4];
    int tid = threadIdx.x;
    int tx = tid & 7;       // N dir: 8 groups of 8 cols
    int ty = tid >> 3;      // M dir: 16 groups of 8 rows
    int row0 = blockIdx.y * BM;
    int col0 = blockIdx.x * BN;

    float acc[8][8] = {};
    for (int k0 = 0; k0 < K; k0 += BK) {
        // A tile: 128x16, coalesced (consecutive tids -> consecutive k within row)
        #pragma unroll
        for (int t = 0; t < 16; t++) {
            int idx = tid + t * 128;
            int kk = idx & 15;
            int r  = idx >> 4;
            int gm = row0 + r, gk = k0 + kk;
            As[kk][r] = (gm < M && gk < K) ? A[(size_t)gm * K + gk] : 0.0f;
        }
        // B tile: 16x64, coalesced rows
        #pragma unroll
        for (int t = 0; t < 8; t++) {
            int idx = tid + t * 128;
            int kk = idx >> 6;
            int n  = idx & 63;
            int gk = k0 + kk, gn = col0 + n;
            Bs[kk][n] = (gk < K && gn < N) ? B[(size_t)gk * N + gn] : 0.0f;
        }
        __syncthreads();
        #pragma unroll
        for (int kk = 0; kk < BK; kk++) {
            float4 a0 = *(const float4*)&As[kk][ty * 8];
            float4 a1 = *(const float4*)&As[kk][ty * 8 + 4];
            float4 b0 = *(const float4*)&Bs[kk][tx * 8];
            float4 b1 = *(const float4*)&Bs[kk][tx * 8 + 4];
            float a[8] = {a0.x, a0.y, a0.z, a0.w, a1.x, a1.y, a1.z, a1.w};
            float b[8] = {b0.x, b0.y, b0.z, b0.w, b1.x, b1.y, b1.z, b1.w};
            #pragma unroll
            for (int i = 0; i < 8; i++)
                #pragma unroll
                for (int j = 0; j < 8; j++)
                    acc[i][j] = fmaf(a[i], b[j], acc[i][j]);
        }
        __syncthreads();
    }
    #pragma unroll
    for (int i = 0; i < 8; i++) {
        int gm = row0 + ty * 8 + i;
        if (gm >= M) continue;
        float sc = (mode == 3) ? scale[gm] : 1.0f;
        #pragma unroll
        for (int j = 0; j < 8; j++) {
            int gn = col0 + tx * 8 + j;
            if (gn >= N) continue;
            float v = acc[i][j];
            if (mode == 3) v *= sc;
            else if (mode >= 1) { v += bias[gn]; if (mode == 2) v = fmaxf(v, 0.0f); }
            C[(size_t)gm * N + gn] = v;
        }
    }
}

// ---------------- GCN aggregation (CSR gather, fused self+bias+relu) ----------------
// B holds xw*dinv. out[i] = relu( (sum_{s->i} B[s] + B[i]) * dinv[i] + bias )
template <int DO>
__global__ __launch_bounds__(256) void gcn_agg_kernel(
    const float* __restrict__ Bm, const int* __restrict__ rowstart,
    const int* __restrict__ cnt, const int* __restrict__ csr_src,
    const float* __restrict__ dinv, const float* __restrict__ bias,
    float* __restrict__ out) {
    int warp = (blockIdx.x * blockDim.x + threadIdx.x) >> 5;
    int lane = threadIdx.x & 31;
    if (warp >= N_NODES) return;
    constexpr int NF = (DO + 31) / 32;
    float acc[NF];
    #pragma unroll
    for (int i = 0; i < NF; i++) acc[i] = 0.0f;

    int start = rowstart[warp];
    int end = start + cnt[warp];
    for (int j = start; j < end; j++) {
        int s = csr_src[j];
        const float* __restrict__ br = Bm + (size_t)s * DO;
        #pragma unroll
        for (int i = 0; i < NF; i++) {
            int f = lane + 32 * i;
            if (f < DO) acc[i] += __ldg(&br[f]);
        }
    }
    float di = dinv[warp];
    const float* __restrict__ selfr = Bm + (size_t)warp * DO;
    float* __restrict__ orow = out + (size_t)warp * DO;
    #pragma unroll
    for (int i = 0; i < NF; i++) {
        int f = lane + 32 * i;
        if (f < DO)
            orow[f] = fmaxf((acc[i] + selfr[f]) * di + bias[f], 0.0f);
    }
}

// ---------------- mean pool ----------------
__global__ __launch_bounds__(256) void pool_kernel(
    const float* __restrict__ X, const int* __restrict__ batch,
    float* __restrict__ pooled, float* __restrict__ gcnt) {
    int warp = (blockIdx.x * blockDim.x + threadIdx.x) >> 5;
    int lane = threadIdx.x & 31;
    if (warp >= N_NODES) return;
    int g = batch[warp];
    if (lane == 0) atomicAdd(&gcnt[g], 1.0f);
    const float* __restrict__ xrow = X + (size_t)warp * D3;
    float* __restrict__ prow = pooled + (size_t)g * D3;
    for (int f = lane; f < D3; f += 32)
        atomicAdd(&prow[f], xrow[f]);
}
__global__ void pool_div_kernel(float* __restrict__ pooled, const float* __restrict__ gcnt) {
    int idx = blockIdx.x * blockDim.x + threadIdx.x;
    if (idx >= N_GRAPHS * D3) return;
    int g = idx / D3;
    pooled[idx] /= fmaxf(gcnt[g], 1.0f);
}

// ---------------- gate + fuse: one warp per graph ----------------
__global__ __launch_bounds__(256) void gate_fuse_kernel(
    const float* __restrict__ pooled, const float* __restrict__ gvec,
    const float* __restrict__ Wgate, const float* __restrict__ bgate,
    float* __restrict__ fused) {
    int warp = (blockIdx.x * blockDim.x + threadIdx.x) >> 5;
    int lane = threadIdx.x & 31;
    if (warp >= N_GRAPHS) return;
    const float* __restrict__ prow = pooled + (size_t)warp * D3;
    const float* __restrict__ grow = gvec + (size_t)warp * D3;
    float t = 0.0f;
    for (int f = lane; f < D3; f += 32)
        t += prow[f] * Wgate[f] + grow[f] * Wgate[D3 + f];
    #pragma unroll
    for (int off = 16; off > 0; off >>= 1)
        t += __shfl_xor_sync(0xFFFFFFFF, t, off);
    t += bgate[0];
    float gate = 1.0f / (1.0f + expf(-t));
    gate = __shfl_sync(0xFFFFFFFF, gate, 0);
    float* __restrict__ frow = fused + (size_t)warp * D3;
    for (int f = lane; f < D3; f += 32)
        frow[f] = gate * grow[f] + (1.0f - gate) * prow[f];
}

// ---------------- host ----------------
static inline int cdiv(int a, int b) { return (a + b - 1) / b; }

extern "C" void kernel_launch(void* const* d_in, const int* in_sizes, int n_in,
                              void* d_out, int out_size) {
    const float* mol_x  = (const float*)d_in[0];
    const int*   edges  = (const int*)d_in[1];
    const int*   batch  = (const int*)d_in[2];
    const float* gemb   = (const float*)d_in[3];
    const float* W1     = (const float*)d_in[4];
    const float* b1     = (const float*)d_in[5];
    const float* W2     = (const float*)d_in[6];
    const float* b2     = (const float*)d_in[7];
    const float* W3     = (const float*)d_in[8];
    const float* b3     = (const float*)d_in[9];
    const float* Wfc1   = (const float*)d_in[10];
    const float* bfc1   = (const float*)d_in[11];
    const float* Wfc2   = (const float*)d_in[12];
    const float* bfc2   = (const float*)d_in[13];
    const float* Wproj  = (const float*)d_in[14];
    const float* bproj  = (const float*)d_in[15];
    const float* Wgate  = (const float*)d_in[16];
    const float* bgate  = (const float*)d_in[17];
    float* out = (float*)d_out;

    const int* src = edges;
    const int* dst = edges + N_EDGES;

    float *pA, *pB, *pdinv, *ppool, *pgcnt, *pg, *pfused, *ph;
    int *pcnt, *prowstart, *pcursor, *pblocksum, *pcsr;
    cudaGetSymbolAddress((void**)&pA, g_A);
    cudaGetSymbolAddress((void**)&pB, g_B);
    cudaGetSymbolAddress((void**)&pdinv, g_dinv);
    cudaGetSymbolAddress((void**)&pcnt, g_cnt);
    cudaGetSymbolAddress((void**)&prowstart, g_rowstart);
    cudaGetSymbolAddress((void**)&pcursor, g_cursor);
    cudaGetSymbolAddress((void**)&pblocksum, g_blocksum);
    cudaGetSymbolAddress((void**)&pcsr, g_csr_src);
    cudaGetSymbolAddress((void**)&ppool, g_pool);
    cudaGetSymbolAddress((void**)&pgcnt, g_gcnt);
    cudaGetSymbolAddress((void**)&pg, g_g);
    cudaGetSymbolAddress((void**)&pfused, g_fused);
    cudaGetSymbolAddress((void**)&ph, g_h);

    // ---- degree + dinv + CSR build ----
    zero_i_kernel<<<cdiv(N_NODES, 256), 256>>>(pcnt, N_NODES);
    deg_count_kernel<<<cdiv(N_EDGES, 256), 256>>>(dst, pcnt);
    dinv_kernel<<<cdiv(N_NODES, 256), 256>>>(pcnt, pdinv);
    int nblk = cdiv(N_NODES, SCAN_T * SCAN_V);  // 98
    scan1_kernel<<<nblk, SCAN_T>>>(pcnt, prowstart, pblocksum, N_NODES);
    scan2_kernel<<<1, 32>>>(pblocksum, nblk);
    scan3_kernel<<<cdiv(N_NODES, 256), 256>>>(prowstart, pblocksum, pcursor, N_NODES);
    csr_scatter_kernel<<<cdiv(N_EDGES, 256), 256>>>(src, dst, pcursor, pcsr);

    // ---- GCN layer 1: mol_x [N,78] -> A [N,78] ----
    {
        dim3 grid(cdiv(D1, BN), cdiv(N_NODES, BM));
        gemm_kernel<<<grid, 128>>>(mol_x, W1, nullptr, pdinv, pB, N_NODES, D0, D1, 3);
        gcn_agg_kernel<D1><<<cdiv(N_NODES * 32, 256), 256>>>(pB, prowstart, pcnt, pcsr, pdinv, b1, pA);
    }
    // ---- GCN layer 2: A [N,78] -> A [N,156] ----
    {
        dim3 grid(cdiv(D2, BN), cdiv(N_NODES, BM));
        gemm_kernel<<<grid, 128>>>(pA, W2, nullptr, pdinv, pB, N_NODES, D1, D2, 3);
        gcn_agg_kernel<D2><<<cdiv(N_NODES * 32, 256), 256>>>(pB, prowstart, pcnt, pcsr, pdinv, b2, pA);
    }
    // ---- GCN layer 3: A [N,156] -> A [N,312] ----
    {
        dim3 grid(cdiv(D3, BN), cdiv(N_NODES, BM));
        gemm_kernel<<<grid, 128>>>(pA, W3, nullptr, pdinv, pB, N_NODES, D2, D3, 3);
        gcn_agg_kernel<D3><<<cdiv(N_NODES * 32, 256), 256>>>(pB, prowstart, pcnt, pcsr, pdinv, b3, pA);
    }

    // ---- mean pool ----
    {
        size_t np = (size_t)N_GRAPHS * D3;
        zero_f_kernel<<<(unsigned)((np + 255) / 256), 256>>>(ppool, np);
        zero_f_kernel<<<cdiv(N_GRAPHS, 256), 256>>>(pgcnt, (size_t)N_GRAPHS);
        pool_kernel<<<cdiv(N_NODES * 32, 256), 256>>>(pA, batch, ppool, pgcnt);
        pool_div_kernel<<<cdiv(N_GRAPHS * D3, 256), 256>>>(ppool, pgcnt);
    }

    // ---- g = global_emb @ Wproj + bproj  [4096,128]@[128,312] ----
    {
        dim3 grid(cdiv(D3, BN), cdiv(N_GRAPHS, BM));
        gemm_kernel<<<grid, 128>>>(gemb, Wproj, bproj, nullptr, pg, N_GRAPHS, 128, D3, 1);
    }

    // ---- gate + fuse ----
    gate_fuse_kernel<<<cdiv(N_GRAPHS * 32, 256), 256>>>(ppool, pg, Wgate, bgate, pfused);

    // ---- fc1: relu(fused @ Wfc1 + bfc1)  [4096,312]@[312,1024] ----
    {
        dim3 grid(cdiv(DH, BN), cdiv(N_GRAPHS, BM));
        gemm_kernel<<<grid, 128>>>(pfused, Wfc1, bfc1, nullptr, ph, N_GRAPHS, D3, DH, 2);
    }

    // ---- fc2: h @ Wfc2 + bfc2  [4096,1024]@[1024,128] -> out ----
    {
        dim3 grid(cdiv(DOUT, BN), cdiv(N_GRAPHS, BM));
        gemm_kernel<<<grid, 128>>>(ph, Wfc2, bfc2, nullptr, out, N_GRAPHS, DH, DOUT, 1);
    }
}